// round 14
// baseline (speedup 1.0000x reference)
#include <cuda_runtime.h>
#include <cuda_bf16.h>
#include <cstdint>

// Shapes (fixed): B=2, D=H=W=64, L=262144, C=64, WS=2, S=8, NH=8, HD=8, MLP=256

__device__ __forceinline__ uint32_t pk(float lo, float hi) {
    uint32_t r;
    asm("cvt.rn.bf16x2.f32 %0, %1, %2;" : "=r"(r) : "f"(hi), "f"(lo));
    return r;
}

__device__ __forceinline__ float2 upk(uint32_t u) {
    __nv_bfloat162 b = *reinterpret_cast<__nv_bfloat162*>(&u);
    return __bfloat1622float2(b);
}

__device__ __forceinline__ uint32_t s2u(const void* p) {
    return (uint32_t)__cvta_generic_to_shared(p);
}

__device__ __forceinline__ void ldsm_x4(uint32_t* r, uint32_t addr) {
    asm volatile("ldmatrix.sync.aligned.m8n8.x4.shared.b16 {%0,%1,%2,%3},[%4];"
                 : "=r"(r[0]), "=r"(r[1]), "=r"(r[2]), "=r"(r[3]) : "r"(addr));
}

__device__ __forceinline__ void ldsm_x4t(uint32_t* r, uint32_t addr) {
    asm volatile("ldmatrix.sync.aligned.m8n8.x4.trans.shared.b16 {%0,%1,%2,%3},[%4];"
                 : "=r"(r[0]), "=r"(r[1]), "=r"(r[2]), "=r"(r[3]) : "r"(addr));
}

__device__ __forceinline__ void mma16(float* d, const uint32_t* a, const uint32_t* b) {
    asm volatile(
        "mma.sync.aligned.m16n8k16.row.col.f32.bf16.bf16.f32 "
        "{%0,%1,%2,%3},{%4,%5,%6,%7},{%8,%9},{%0,%1,%2,%3};\n"
        : "+f"(d[0]), "+f"(d[1]), "+f"(d[2]), "+f"(d[3])
        : "r"(a[0]), "r"(a[1]), "r"(a[2]), "r"(a[3]), "r"(b[0]), "r"(b[1]));
}

__device__ __forceinline__ float gelu_fast(float h) {
    float u = 0.7978845608028654f * fmaf(0.044715f * h, h * h, h);
    float t;
    asm("tanh.approx.f32 %0, %1;" : "=f"(t) : "f"(u));
    return 0.5f * h * (1.f + t);
}

#define ROWB 528   // s_qkv row stride in bytes: q 256B f32 | k 128B bf16 | v 128B bf16 | pad

// ---------------------------------------------------------------------------
// Attention kernel (persistent): weights converted+staged ONCE per block from
// fp32, loop over window-groups. 256 threads, 8 windows/iter, 3 blocks/SM.
// ---------------------------------------------------------------------------
__global__ void __launch_bounds__(256, 3) swin_attn_bf16_kernel(
    const float* __restrict__ x,
    const float* __restrict__ n1g, const float* __restrict__ n1b,
    const float* __restrict__ qkvw, const float* __restrict__ qkvb,
    const float* __restrict__ rpb,
    const float* __restrict__ projw, const float* __restrict__ projb,
    float* __restrict__ x1)
{
    extern __shared__ __align__(16) uint8_t smem[];
    uint8_t* s_a   = smem;                       // 8192 B
    uint8_t* s_w   = smem + 8192;                // 32768 B
    uint8_t* s_qkv = smem + 40960;               // 64*528 B

    const int tid   = threadIdx.x;
    const int lane  = tid & 31;
    const int wrp   = tid >> 5;
    const int g     = lane >> 2, tg = lane & 3;
    const int l15   = lane & 15;
    const int hi    = lane >> 4;
    const int sw    = lane & 7;
    const int R     = (wrp & 3) << 4;
    const int Cb    = (wrp >> 2) << 5;

    const uint32_t ua = s2u(s_a);
    const uint32_t uw = s2u(s_w);

    // ---- stage ALL weights once: fp32 -> bf16 swizzled (cvt-kernel formulas) ----
#pragma unroll
    for (int it = 0; it < 8; ++it) {
        int slot = it * 256 + tid;               // 0..2047
        int ch = slot >> 9;                      // 0..2 = qkv chunk, 3 = proj
        int s  = slot & 511;
        int k = s >> 3, c = s & 7;
        const float* p = (ch < 3) ? (qkvw + k * 192 + ch * 64 + c * 8)
                                  : (projw + k * 64 + c * 8);
        float4 u = *(const float4*)p;
        float4 v = *(const float4*)(p + 4);
        uint4 o = { pk(u.x, u.y), pk(u.z, u.w), pk(v.x, v.y), pk(v.z, v.w) };
        *(uint4*)(s_w + ch * 8192 + k * 128 + ((c ^ (k & 7)) << 4)) = o;
    }

    const int colB0 = ((((wrp >> 2) << 2) + 0 + hi) ^ sw) << 4;
    const int colB1 = ((((wrp >> 2) << 2) + 2 + hi) ^ sw) << 4;
    const uint32_t rowAoff = (uint32_t)(R + l15) * 128;

    for (int gb = blockIdx.x; gb < 8192; gb += gridDim.x) {
        __syncthreads();   // [0] protect s_a/s_qkv across iterations (and weights on iter 0)

        // ---- Phase 1: shifted gather + LayerNorm1 -> s_a ----
        {
            const int m  = tid >> 2;
            const int cq = (tid & 3) << 4;
            const int gwin = gb * 8 + (m >> 3);
            const int bb   = gwin >> 15;
            const int w15  = gwin & 32767;
            const int pz = w15 >> 10, py = (w15 >> 5) & 31, px = w15 & 31;
            const int s = m & 7;
            const int dz = ((pz << 1) + (s >> 2) + 1) & 63;
            const int dy = ((py << 1) + ((s >> 1) & 1) + 1) & 63;
            const int dx = ((px << 1) + (s & 1) + 1) & 63;
            const float* src = x + (bb << 24) + ((((dz << 12) | (dy << 6) | dx)) << 6) + cq;

            float4 v[4];
            float sm = 0.f, sq = 0.f;
#pragma unroll
            for (int f = 0; f < 4; ++f) {
                v[f] = *(const float4*)(src + f * 4);
                sm += v[f].x + v[f].y + v[f].z + v[f].w;
                sq += v[f].x * v[f].x + v[f].y * v[f].y + v[f].z * v[f].z + v[f].w * v[f].w;
            }
            sm += __shfl_xor_sync(0xffffffffu, sm, 1);
            sq += __shfl_xor_sync(0xffffffffu, sq, 1);
            sm += __shfl_xor_sync(0xffffffffu, sm, 2);
            sq += __shfl_xor_sync(0xffffffffu, sq, 2);
            float mu = sm * 0.015625f;
            float rs = rsqrtf(fmaxf(sq * 0.015625f - mu * mu, 0.f) + 1e-5f);
            const int c0 = (tid & 3) << 1;
#pragma unroll
            for (int f = 0; f < 2; ++f) {
                float4 va = v[2 * f], vb = v[2 * f + 1];
                float4 g0 = *(const float4*)(n1g + cq + f * 8);
                float4 g1 = *(const float4*)(n1g + cq + f * 8 + 4);
                float4 b0 = *(const float4*)(n1b + cq + f * 8);
                float4 b1 = *(const float4*)(n1b + cq + f * 8 + 4);
                uint4 o;
                o.x = pk((va.x - mu) * rs * g0.x + b0.x, (va.y - mu) * rs * g0.y + b0.y);
                o.y = pk((va.z - mu) * rs * g0.z + b0.z, (va.w - mu) * rs * g0.w + b0.w);
                o.z = pk((vb.x - mu) * rs * g1.x + b1.x, (vb.y - mu) * rs * g1.y + b1.y);
                o.w = pk((vb.z - mu) * rs * g1.z + b1.z, (vb.w - mu) * rs * g1.w + b1.w);
                *(uint4*)(s_a + m * 128 + (((c0 + f) ^ (m & 7)) << 4)) = o;
            }
        }
        __syncthreads();   // [1]

        // ---- Phase 2: QKV = xn @ qkvw (3 chunks) ----
#pragma unroll
        for (int nc = 0; nc < 3; ++nc) {
            float f1[4][4];
#pragma unroll
            for (int j = 0; j < 4; ++j)
#pragma unroll
                for (int r = 0; r < 4; ++r) f1[j][r] = 0.f;

#pragma unroll
            for (int k0 = 0; k0 < 4; ++k0) {
                uint32_t A[4], Bf[2][4];
                int colA = (((k0 << 1) + hi) ^ sw) << 4;
                ldsm_x4(A, ua + rowAoff + colA);
                uint32_t rb = uw + (uint32_t)(nc * 8192 + k0 * 2048 + l15 * 128);
                ldsm_x4t(Bf[0], rb + colB0);
                ldsm_x4t(Bf[1], rb + colB1);
#pragma unroll
                for (int j = 0; j < 4; ++j)
                    mma16(f1[j], A, &Bf[j >> 1][(j & 1) * 2]);
            }
            const int m0 = R + g, m1 = m0 + 8;
#pragma unroll
            for (int j = 0; j < 4; ++j) {
                int col = Cb + j * 8 + tg * 2;
                float b0 = __ldg(qkvb + nc * 64 + col);
                float b1 = __ldg(qkvb + nc * 64 + col + 1);
                if (nc == 0) {
                    const float scale = 0.35355339059327373f;
                    float2 o0 = { (f1[j][0] + b0) * scale, (f1[j][1] + b1) * scale };
                    float2 o1 = { (f1[j][2] + b0) * scale, (f1[j][3] + b1) * scale };
                    *(float2*)(s_qkv + m0 * ROWB + col * 4) = o0;
                    *(float2*)(s_qkv + m1 * ROWB + col * 4) = o1;
                } else {
                    int off = (nc == 1) ? 256 : 384;
                    *(uint32_t*)(s_qkv + m0 * ROWB + off + col * 2) =
                        pk(f1[j][0] + b0, f1[j][1] + b1);
                    *(uint32_t*)(s_qkv + m1 * ROWB + off + col * 2) =
                        pk(f1[j][2] + b0, f1[j][3] + b1);
                }
            }
        }
        __syncthreads();   // [2]

        // ---- Phase 3: softmax (fp32 math, bf16 k/v), bitmask mask ----
#pragma unroll
        for (int r = 0; r < 2; ++r) {
            const int tk  = tid + r * 256;
            const int win = tk >> 6, hh = (tk >> 3) & 7, qi = tk & 7;
            const int gwin = gb * 8 + win;
            const int w15  = gwin & 32767;
            const int pz = w15 >> 10, py = (w15 >> 5) & 31, px = w15 & 31;

            const uint8_t* qr = s_qkv + (win * 8 + qi) * ROWB + hh * 32;
            float4 q0 = *(const float4*)qr;
            float4 q1 = *(const float4*)(qr + 16);

            const int xm = ((pz == 31) ? 4 : 0) | ((py == 31) ? 2 : 0) | ((px == 31) ? 1 : 0);

            const int cf0p = (hh >> 1) & 1, cf1p = hh >> 2, cf2p = hh & 1;
            const int cf0q = (qi >> 1) & 1, cf1q = qi >> 2, cf2q = qi & 1;
            const int ridx = 3 * (cf0p - cf0q + 1) + (cf1p - cf1q + 1) + (cf2p - cf2q + 1);

            float rbv[8];
            {
                float4 r0 = __ldg((const float4*)(rpb + ridx * 8));
                float4 r1 = __ldg((const float4*)(rpb + ridx * 8 + 4));
                rbv[0] = r0.x; rbv[1] = r0.y; rbv[2] = r0.z; rbv[3] = r0.w;
                rbv[4] = r1.x; rbv[5] = r1.y; rbv[6] = r1.z; rbv[7] = r1.w;
            }

            float sc[8];
            float den = 0.f;
#pragma unroll
            for (int j = 0; j < 8; ++j) {
                uint4 kb = *(const uint4*)(s_qkv + (win * 8 + j) * ROWB + 256 + hh * 16);
                float2 k0 = upk(kb.x), k1 = upk(kb.y), k2 = upk(kb.z), k3 = upk(kb.w);
                float a;
                a = q0.x * k0.x;
                a = fmaf(q0.y, k0.y, a);
                a = fmaf(q0.z, k1.x, a);
                a = fmaf(q0.w, k1.y, a);
                a = fmaf(q1.x, k2.x, a);
                a = fmaf(q1.y, k2.y, a);
                a = fmaf(q1.z, k3.x, a);
                a = fmaf(q1.w, k3.y, a);
                a += rbv[j];
                if ((j ^ qi) & xm) a -= 100.f;
                sc[j] = __expf(a);
                den += sc[j];
            }
            float inv = 1.f / den;
#pragma unroll
            for (int j = 0; j < 8; ++j) sc[j] *= inv;

            float4 o0 = {0.f, 0.f, 0.f, 0.f}, o1 = {0.f, 0.f, 0.f, 0.f};
#pragma unroll
            for (int j = 0; j < 8; ++j) {
                uint4 vb = *(const uint4*)(s_qkv + (win * 8 + j) * ROWB + 384 + hh * 16);
                float2 v0 = upk(vb.x), v1 = upk(vb.y), v2 = upk(vb.z), v3 = upk(vb.w);
                o0.x = fmaf(sc[j], v0.x, o0.x);
                o0.y = fmaf(sc[j], v0.y, o0.y);
                o0.z = fmaf(sc[j], v1.x, o0.z);
                o0.w = fmaf(sc[j], v1.y, o0.w);
                o1.x = fmaf(sc[j], v2.x, o1.x);
                o1.y = fmaf(sc[j], v2.y, o1.y);
                o1.z = fmaf(sc[j], v3.x, o1.z);
                o1.w = fmaf(sc[j], v3.y, o1.w);
            }
            const int m = win * 8 + qi;
            uint4 ob;
            ob.x = pk(o0.x, o0.y);
            ob.y = pk(o0.z, o0.w);
            ob.z = pk(o1.x, o1.y);
            ob.w = pk(o1.z, o1.w);
            *(uint4*)(s_a + m * 128 + ((hh ^ (m & 7)) << 4)) = ob;
        }
        __syncthreads();   // [3]

        // ---- Phase 4: proj GEMM + window-reverse scatter + residual ----
        {
            float c2[4][4];
#pragma unroll
            for (int j = 0; j < 4; ++j)
#pragma unroll
                for (int r = 0; r < 4; ++r) c2[j][r] = 0.f;

#pragma unroll
            for (int k0 = 0; k0 < 4; ++k0) {
                uint32_t A[4], Bf[2][4];
                int colA = (((k0 << 1) + hi) ^ sw) << 4;
                ldsm_x4(A, ua + rowAoff + colA);
                uint32_t rb = uw + (uint32_t)(24576 + k0 * 2048 + l15 * 128);
                ldsm_x4t(Bf[0], rb + colB0);
                ldsm_x4t(Bf[1], rb + colB1);
#pragma unroll
                for (int j = 0; j < 4; ++j)
                    mma16(c2[j], A, &Bf[j >> 1][(j & 1) * 2]);
            }

            int offr[2];
#pragma unroll
            for (int i = 0; i < 2; ++i) {
                int m = R + g + i * 8;
                int gwin = gb * 8 + (m >> 3);
                int bb   = gwin >> 15;
                int w15  = gwin & 32767;
                int pz = w15 >> 10, py = (w15 >> 5) & 31, px = w15 & 31;
                int s = m & 7;
                int px1 = ((px & 15) << 1) | (s >> 2);
                int py1 = ((py & 15) << 1) | (px >> 4);
                int a2  = (py >> 4) & 1;
                int b2  = (s >> 1) & 1;
                int cc2 = s & 1;
                int gg = (pz << 5) + py1;
                gg = (gg << 1) + b2;
                gg = (gg << 1) + a2;
                gg = (gg << 5) + px1;
                gg = (gg << 1) + cc2;
                int dd  = ((gg >> 12) + 1) & 63;
                int hh2 = ((gg >> 6) + 1) & 63;
                int ww2 = (gg + 1) & 63;
                offr[i] = (bb << 24) + ((((dd << 12) | (hh2 << 6) | ww2)) << 6);
            }
#pragma unroll
            for (int j = 0; j < 4; ++j) {
                int col = Cb + j * 8 + tg * 2;
                float b0 = __ldg(projb + col);
                float b1 = __ldg(projb + col + 1);
#pragma unroll
                for (int i = 0; i < 2; ++i) {
                    float2 rx = *(const float2*)(x + offr[i] + col);
                    float2 o;
                    o.x = c2[j][2 * i]     + b0 + rx.x;
                    o.y = c2[j][2 * i + 1] + b1 + rx.y;
                    *(float2*)(x1 + offr[i] + col) = o;
                }
            }
        }
    }
}

// ---------------------------------------------------------------------------
// MLP kernel (persistent): weights converted+staged once per block from fp32,
// loop over token-groups. 256 threads, 128 tokens/iter, 80KB smem, 2 blk/SM.
// ---------------------------------------------------------------------------
__global__ void __launch_bounds__(256, 2) swin_mlp_bf16_kernel(
    float* __restrict__ io,
    const float* __restrict__ n2g, const float* __restrict__ n2b,
    const float* __restrict__ w1, const float* __restrict__ b1,
    const float* __restrict__ w2, const float* __restrict__ b2)
{
    extern __shared__ __align__(16) uint8_t smem[];
    uint8_t* s_a  = smem;                   // 16384
    uint8_t* s_w1 = smem + 16384;           // 32768
    uint8_t* s_w2 = smem + 49152;           // 32768

    const int tid  = threadIdx.x;
    const int lane = tid & 31;
    const int wrp  = tid >> 5;
    const int g    = lane >> 2, tg = lane & 3;
    const int l15  = lane & 15;
    const int hi   = lane >> 4;
    const int sw   = lane & 7;

    const uint32_t uaa = s2u(s_a);
    const uint32_t uw1 = s2u(s_w1);
    const uint32_t uw2 = s2u(s_w2);

    // ---- stage ALL weights once: fp32 -> bf16 swizzled (cvt-kernel formulas) ----
#pragma unroll
    for (int it = 0; it < 8; ++it) {
        int slot = it * 256 + tid;          // 0..2047
        int nc = slot >> 9, s = slot & 511;
        int k = s >> 3, c = s & 7;
        int dst = nc * 8192 + k * 128 + ((c ^ (k & 7)) << 4);
        {
            const float* p = w1 + k * 256 + nc * 64 + c * 8;
            float4 u = *(const float4*)p;
            float4 v = *(const float4*)(p + 4);
            uint4 o = { pk(u.x, u.y), pk(u.z, u.w), pk(v.x, v.y), pk(v.z, v.w) };
            *(uint4*)(s_w1 + dst) = o;
        }
        {
            const float* p = w2 + (nc * 64 + k) * 64 + c * 8;
            float4 u = *(const float4*)p;
            float4 v = *(const float4*)(p + 4);
            uint4 o = { pk(u.x, u.y), pk(u.z, u.w), pk(v.x, v.y), pk(v.z, v.w) };
            *(uint4*)(s_w2 + dst) = o;
        }
    }

    const uint32_t rowA = (uint32_t)(wrp * 16 + l15) * 128;

    for (int tb = blockIdx.x; tb < 4096; tb += gridDim.x) {
        const int base = tb * 8192;
        __syncthreads();   // protect s_a across iterations (and weights on iter 0)

        // ---- LayerNorm2 -> s_a (bf16 swizzled) ----
        {
            const int mb = tid >> 2;
            const int cq = (tid & 3) << 4;
            const int c0 = (tid & 3) << 1;
            float4 g0 = *(const float4*)(n2g + cq);
            float4 g1 = *(const float4*)(n2g + cq + 4);
            float4 g2 = *(const float4*)(n2g + cq + 8);
            float4 g3 = *(const float4*)(n2g + cq + 12);
            float4 e0 = *(const float4*)(n2b + cq);
            float4 e1 = *(const float4*)(n2b + cq + 4);
            float4 e2 = *(const float4*)(n2b + cq + 8);
            float4 e3 = *(const float4*)(n2b + cq + 12);
#pragma unroll
            for (int p = 0; p < 2; ++p) {
                int m = p * 64 + mb;
                const float* src = io + base + m * 64 + cq;
                float4 v[4];
                float sm = 0.f, sq = 0.f;
#pragma unroll
                for (int f = 0; f < 4; ++f) {
                    v[f] = *(const float4*)(src + f * 4);
                    sm += v[f].x + v[f].y + v[f].z + v[f].w;
                    sq += v[f].x * v[f].x + v[f].y * v[f].y + v[f].z * v[f].z + v[f].w * v[f].w;
                }
                sm += __shfl_xor_sync(0xffffffffu, sm, 1);
                sq += __shfl_xor_sync(0xffffffffu, sq, 1);
                sm += __shfl_xor_sync(0xffffffffu, sm, 2);
                sq += __shfl_xor_sync(0xffffffffu, sq, 2);
                float mu = sm * 0.015625f;
                float rs = rsqrtf(fmaxf(sq * 0.015625f - mu * mu, 0.f) + 1e-5f);
                uint4 o;
                o.x = pk((v[0].x - mu) * rs * g0.x + e0.x, (v[0].y - mu) * rs * g0.y + e0.y);
                o.y = pk((v[0].z - mu) * rs * g0.z + e0.z, (v[0].w - mu) * rs * g0.w + e0.w);
                o.z = pk((v[1].x - mu) * rs * g1.x + e1.x, (v[1].y - mu) * rs * g1.y + e1.y);
                o.w = pk((v[1].z - mu) * rs * g1.z + e1.z, (v[1].w - mu) * rs * g1.w + e1.w);
                *(uint4*)(s_a + m * 128 + ((c0 ^ (m & 7)) << 4)) = o;
                o.x = pk((v[2].x - mu) * rs * g2.x + e2.x, (v[2].y - mu) * rs * g2.y + e2.y);
                o.y = pk((v[2].z - mu) * rs * g2.z + e2.z, (v[2].w - mu) * rs * g2.w + e2.w);
                o.z = pk((v[3].x - mu) * rs * g3.x + e3.x, (v[3].y - mu) * rs * g3.y + e3.y);
                o.w = pk((v[3].z - mu) * rs * g3.z + e3.z, (v[3].w - mu) * rs * g3.w + e3.w);
                *(uint4*)(s_a + m * 128 + (((c0 + 1) ^ (m & 7)) << 4)) = o;
            }
        }
        __syncthreads();

        uint32_t Afr[4][4];
#pragma unroll
        for (int k0 = 0; k0 < 4; ++k0)
            ldsm_x4(Afr[k0], uaa + rowA + ((((k0 << 1) + hi) ^ sw) << 4));

        float c2[8][4];
#pragma unroll
        for (int j = 0; j < 8; ++j)
#pragma unroll
            for (int r = 0; r < 4; ++r) c2[j][r] = 0.f;

#pragma unroll
        for (int nc = 0; nc < 4; ++nc) {
            float f1[8][4];
#pragma unroll
            for (int j = 0; j < 8; ++j)
#pragma unroll
                for (int r = 0; r < 4; ++r) f1[j][r] = 0.f;

#pragma unroll
            for (int k0 = 0; k0 < 4; ++k0) {
                uint32_t Bf[4][4];
                uint32_t rb = uw1 + (uint32_t)(nc * 8192 + k0 * 2048 + l15 * 128);
#pragma unroll
                for (int t = 0; t < 4; ++t)
                    ldsm_x4t(Bf[t], rb + ((((t << 1) + hi) ^ sw) << 4));
#pragma unroll
                for (int j = 0; j < 8; ++j)
                    mma16(f1[j], Afr[k0], &Bf[j >> 1][(j & 1) * 2]);
            }

            uint32_t Ha[4][4];
#pragma unroll
            for (int j = 0; j < 8; ++j) {
                int col0 = nc * 64 + j * 8 + tg * 2;
                float bb0 = __ldg(b1 + col0);
                float bb1 = __ldg(b1 + col0 + 1);
                float h0 = gelu_fast(f1[j][0] + bb0);
                float h1 = gelu_fast(f1[j][1] + bb1);
                float h2 = gelu_fast(f1[j][2] + bb0);
                float h3 = gelu_fast(f1[j][3] + bb1);
                Ha[j >> 1][(j & 1) * 2]     = pk(h0, h1);
                Ha[j >> 1][(j & 1) * 2 + 1] = pk(h2, h3);
            }

#pragma unroll
            for (int kb = 0; kb < 4; ++kb) {
                uint32_t Bf[4][4];
                uint32_t rb = uw2 + (uint32_t)(nc * 8192 + kb * 2048 + l15 * 128);
#pragma unroll
                for (int t = 0; t < 4; ++t)
                    ldsm_x4t(Bf[t], rb + ((((t << 1) + hi) ^ sw) << 4));
#pragma unroll
                for (int j = 0; j < 8; ++j)
                    mma16(c2[j], Ha[kb], &Bf[j >> 1][(j & 1) * 2]);
            }
        }

        {
            int m0 = wrp * 16 + g;
            int m1 = m0 + 8;
#pragma unroll
            for (int j = 0; j < 8; ++j) {
                int col = j * 8 + tg * 2;
                float bb0 = __ldg(b2 + col);
                float bb1 = __ldg(b2 + col + 1);
                float2 r0 = *(const float2*)(io + base + m0 * 64 + col);
                float2 r1 = *(const float2*)(io + base + m1 * 64 + col);
                float2 o0, o1;
                o0.x = c2[j][0] + bb0 + r0.x;
                o0.y = c2[j][1] + bb1 + r0.y;
                o1.x = c2[j][2] + bb0 + r1.x;
                o1.y = c2[j][3] + bb1 + r1.y;
                *(float2*)(io + base + m0 * 64 + col) = o0;
                *(float2*)(io + base + m1 * 64 + col) = o1;
            }
        }
    }
}

extern "C" void kernel_launch(void* const* d_in, const int* in_sizes, int n_in,
                              void* d_out, int out_size)
{
    const float* x     = (const float*)d_in[0];
    const float* n1g   = (const float*)d_in[1];
    const float* n1b   = (const float*)d_in[2];
    const float* qkvw  = (const float*)d_in[3];
    const float* qkvb  = (const float*)d_in[4];
    const float* rpb   = (const float*)d_in[5];
    const float* projw = (const float*)d_in[6];
    const float* projb = (const float*)d_in[7];
    const float* n2g   = (const float*)d_in[8];
    const float* n2b   = (const float*)d_in[9];
    const float* w1    = (const float*)d_in[10];
    const float* b1    = (const float*)d_in[11];
    const float* w2    = (const float*)d_in[12];
    const float* b2    = (const float*)d_in[13];
    float* out = (float*)d_out;

    const int attn_smem = 8192 + 32768 + 64 * ROWB;       // 74752 B
    const int mlp_smem  = 16384 + 32768 + 32768;          // 81920 B
    cudaFuncSetAttribute(swin_attn_bf16_kernel,
                         cudaFuncAttributeMaxDynamicSharedMemorySize, attn_smem);
    cudaFuncSetAttribute(swin_mlp_bf16_kernel,
                         cudaFuncAttributeMaxDynamicSharedMemorySize, mlp_smem);

    // persistent grids: 152 SMs x 3 and x 2
    swin_attn_bf16_kernel<<<456, 256, attn_smem>>>(
        x, n1g, n1b, qkvw, qkvb, rpb, projw, projb, out);
    swin_mlp_bf16_kernel<<<304, 256, mlp_smem>>>(out, n2g, n2b, w1, b1, w2, b2);
}

// round 15
// speedup vs baseline: 1.0323x; 1.0323x over previous
#include <cuda_runtime.h>
#include <cuda_bf16.h>
#include <cstdint>

// Shapes (fixed): B=2, D=H=W=64, L=262144, C=64, WS=2, S=8, NH=8, HD=8, MLP=256

// Pre-converted bf16 weights, stored as the exact swizzled smem image.
__device__ __align__(16) uint8_t gW1b[32768];    // 4 chunks x 8192 B
__device__ __align__(16) uint8_t gW2b[32768];    // 4 chunks x 8192 B
__device__ __align__(16) uint8_t gQKVb[24576];   // 3 chunks x 8192 B
__device__ __align__(16) uint8_t gPROJb[8192];   // 1 chunk

__device__ __forceinline__ uint32_t pk(float lo, float hi) {
    uint32_t r;
    asm("cvt.rn.bf16x2.f32 %0, %1, %2;" : "=r"(r) : "f"(hi), "f"(lo));
    return r;
}

__device__ __forceinline__ float2 upk(uint32_t u) {
    __nv_bfloat162 b = *reinterpret_cast<__nv_bfloat162*>(&u);
    return __bfloat1622float2(b);
}

// 96 blocks x 64 threads
__global__ void __launch_bounds__(64) cvt_weights_kernel(
    const float* __restrict__ qkvw, const float* __restrict__ projw,
    const float* __restrict__ w1,   const float* __restrict__ w2)
{
    const int bid  = blockIdx.x >> 3;
    const int slot = ((blockIdx.x & 7) << 6) + threadIdx.x;   // 0..511
    const int k = slot >> 3, c = slot & 7;
    const int doff = k * 128 + ((c ^ (k & 7)) << 4);

    const float* p;
    uint8_t* dst;
    if (bid < 4) {
        p   = w1 + k * 256 + bid * 64 + c * 8;
        dst = gW1b + bid * 8192 + doff;
    } else if (bid < 8) {
        int nc = bid - 4;
        p   = w2 + (nc * 64 + k) * 64 + c * 8;
        dst = gW2b + nc * 8192 + doff;
    } else if (bid < 11) {
        int nc = bid - 8;
        p   = qkvw + k * 192 + nc * 64 + c * 8;
        dst = gQKVb + nc * 8192 + doff;
    } else {
        p   = projw + k * 64 + c * 8;
        dst = gPROJb + doff;
    }
    float4 u = *(const float4*)p;
    float4 v = *(const float4*)(p + 4);
    uint4 o = { pk(u.x, u.y), pk(u.z, u.w), pk(v.x, v.y), pk(v.z, v.w) };
    *(uint4*)dst = o;
}

__device__ __forceinline__ uint32_t s2u(const void* p) {
    return (uint32_t)__cvta_generic_to_shared(p);
}

__device__ __forceinline__ void ldsm_x4(uint32_t* r, uint32_t addr) {
    asm volatile("ldmatrix.sync.aligned.m8n8.x4.shared.b16 {%0,%1,%2,%3},[%4];"
                 : "=r"(r[0]), "=r"(r[1]), "=r"(r[2]), "=r"(r[3]) : "r"(addr));
}

__device__ __forceinline__ void ldsm_x4t(uint32_t* r, uint32_t addr) {
    asm volatile("ldmatrix.sync.aligned.m8n8.x4.trans.shared.b16 {%0,%1,%2,%3},[%4];"
                 : "=r"(r[0]), "=r"(r[1]), "=r"(r[2]), "=r"(r[3]) : "r"(addr));
}

__device__ __forceinline__ void mma16(float* d, const uint32_t* a, const uint32_t* b) {
    asm volatile(
        "mma.sync.aligned.m16n8k16.row.col.f32.bf16.bf16.f32 "
        "{%0,%1,%2,%3},{%4,%5,%6,%7},{%8,%9},{%0,%1,%2,%3};\n"
        : "+f"(d[0]), "+f"(d[1]), "+f"(d[2]), "+f"(d[3])
        : "r"(a[0]), "r"(a[1]), "r"(a[2]), "r"(a[3]), "r"(b[0]), "r"(b[1]));
}

__device__ __forceinline__ float gelu_fast(float h) {
    float u = 0.7978845608028654f * fmaf(0.044715f * h, h * h, h);
    float t;
    asm("tanh.approx.f32 %0, %1;" : "=f"(t) : "f"(u));
    return 0.5f * h * (1.f + t);
}

#define ROWB 400   // s_qkv row stride: q 128B bf16 | k 128B bf16 | v 128B bf16 | pad

// ---------------------------------------------------------------------------
// Attention kernel (persistent): identity-staged weights, all-bf16 s_qkv.
// 256 threads, 8 windows/iter, 3 blocks/SM, 66.5KB smem (L1D keeps 29KB).
// ---------------------------------------------------------------------------
__global__ void __launch_bounds__(256, 3) swin_attn_bf16_kernel(
    const float* __restrict__ x,
    const float* __restrict__ n1g, const float* __restrict__ n1b,
    const float* __restrict__ qkvb, const float* __restrict__ rpb,
    const float* __restrict__ projb,
    float* __restrict__ x1)
{
    extern __shared__ __align__(16) uint8_t smem[];
    uint8_t* s_a   = smem;                       // 8192 B
    uint8_t* s_w   = smem + 8192;                // 32768 B
    uint8_t* s_qkv = smem + 40960;               // 64*400 B

    const int tid   = threadIdx.x;
    const int lane  = tid & 31;
    const int wrp   = tid >> 5;
    const int g     = lane >> 2, tg = lane & 3;
    const int l15   = lane & 15;
    const int hi    = lane >> 4;
    const int sw    = lane & 7;
    const int R     = (wrp & 3) << 4;
    const int Cb    = (wrp >> 2) << 5;

    const uint32_t ua = s2u(s_a);
    const uint32_t uw = s2u(s_w);

    // ---- stage ALL weights once (identity uint4 copies) ----
    {
        uint4* dw = (uint4*)s_w;
        const uint4* sq = (const uint4*)gQKVb;
        const uint4* sp = (const uint4*)gPROJb;
#pragma unroll
        for (int it = 0; it < 6; ++it) dw[it * 256 + tid] = sq[it * 256 + tid];
        dw[1536 + tid] = sp[tid];
        dw[1792 + tid] = sp[256 + tid];
    }

    const int colB0 = ((((wrp >> 2) << 2) + 0 + hi) ^ sw) << 4;
    const int colB1 = ((((wrp >> 2) << 2) + 2 + hi) ^ sw) << 4;
    const uint32_t rowAoff = (uint32_t)(R + l15) * 128;

    for (int gb = blockIdx.x; gb < 8192; gb += gridDim.x) {
        __syncthreads();   // [0] protect s_a/s_qkv across iterations (and weights on iter 0)

        // ---- Phase 1: shifted gather + LayerNorm1 -> s_a ----
        {
            const int m  = tid >> 2;
            const int cq = (tid & 3) << 4;
            const int gwin = gb * 8 + (m >> 3);
            const int bb   = gwin >> 15;
            const int w15  = gwin & 32767;
            const int pz = w15 >> 10, py = (w15 >> 5) & 31, px = w15 & 31;
            const int s = m & 7;
            const int dz = ((pz << 1) + (s >> 2) + 1) & 63;
            const int dy = ((py << 1) + ((s >> 1) & 1) + 1) & 63;
            const int dx = ((px << 1) + (s & 1) + 1) & 63;
            const float* src = x + (bb << 24) + ((((dz << 12) | (dy << 6) | dx)) << 6) + cq;

            float4 v[4];
            float sm = 0.f, sq = 0.f;
#pragma unroll
            for (int f = 0; f < 4; ++f) {
                v[f] = *(const float4*)(src + f * 4);
                sm += v[f].x + v[f].y + v[f].z + v[f].w;
                sq += v[f].x * v[f].x + v[f].y * v[f].y + v[f].z * v[f].z + v[f].w * v[f].w;
            }
            sm += __shfl_xor_sync(0xffffffffu, sm, 1);
            sq += __shfl_xor_sync(0xffffffffu, sq, 1);
            sm += __shfl_xor_sync(0xffffffffu, sm, 2);
            sq += __shfl_xor_sync(0xffffffffu, sq, 2);
            float mu = sm * 0.015625f;
            float rs = rsqrtf(fmaxf(sq * 0.015625f - mu * mu, 0.f) + 1e-5f);
            const int c0 = (tid & 3) << 1;
#pragma unroll
            for (int f = 0; f < 2; ++f) {
                float4 va = v[2 * f], vb = v[2 * f + 1];
                float4 g0 = *(const float4*)(n1g + cq + f * 8);
                float4 g1 = *(const float4*)(n1g + cq + f * 8 + 4);
                float4 b0 = *(const float4*)(n1b + cq + f * 8);
                float4 b1 = *(const float4*)(n1b + cq + f * 8 + 4);
                uint4 o;
                o.x = pk((va.x - mu) * rs * g0.x + b0.x, (va.y - mu) * rs * g0.y + b0.y);
                o.y = pk((va.z - mu) * rs * g0.z + b0.z, (va.w - mu) * rs * g0.w + b0.w);
                o.z = pk((vb.x - mu) * rs * g1.x + b1.x, (vb.y - mu) * rs * g1.y + b1.y);
                o.w = pk((vb.z - mu) * rs * g1.z + b1.z, (vb.w - mu) * rs * g1.w + b1.w);
                *(uint4*)(s_a + m * 128 + (((c0 + f) ^ (m & 7)) << 4)) = o;
            }
        }
        __syncthreads();   // [1]

        // ---- Phase 2: QKV = xn @ qkvw (3 chunks), all outputs bf16 ----
#pragma unroll
        for (int nc = 0; nc < 3; ++nc) {
            float f1[4][4];
#pragma unroll
            for (int j = 0; j < 4; ++j)
#pragma unroll
                for (int r = 0; r < 4; ++r) f1[j][r] = 0.f;

#pragma unroll
            for (int k0 = 0; k0 < 4; ++k0) {
                uint32_t A[4], Bf[2][4];
                int colA = (((k0 << 1) + hi) ^ sw) << 4;
                ldsm_x4(A, ua + rowAoff + colA);
                uint32_t rb = uw + (uint32_t)(nc * 8192 + k0 * 2048 + l15 * 128);
                ldsm_x4t(Bf[0], rb + colB0);
                ldsm_x4t(Bf[1], rb + colB1);
#pragma unroll
                for (int j = 0; j < 4; ++j)
                    mma16(f1[j], A, &Bf[j >> 1][(j & 1) * 2]);
            }
            const int m0 = R + g, m1 = m0 + 8;
            const int off = nc << 7;             // q 0 | k 128 | v 256
            const float scale = (nc == 0) ? 0.35355339059327373f : 1.0f;
#pragma unroll
            for (int j = 0; j < 4; ++j) {
                int col = Cb + j * 8 + tg * 2;
                float b0 = __ldg(qkvb + nc * 64 + col);
                float b1 = __ldg(qkvb + nc * 64 + col + 1);
                *(uint32_t*)(s_qkv + m0 * ROWB + off + col * 2) =
                    pk((f1[j][0] + b0) * scale, (f1[j][1] + b1) * scale);
                *(uint32_t*)(s_qkv + m1 * ROWB + off + col * 2) =
                    pk((f1[j][2] + b0) * scale, (f1[j][3] + b1) * scale);
            }
        }
        __syncthreads();   // [2]

        // ---- Phase 3: softmax (fp32 math, bf16 q/k/v), bitmask mask ----
#pragma unroll
        for (int r = 0; r < 2; ++r) {
            const int tk  = tid + r * 256;
            const int win = tk >> 6, hh = (tk >> 3) & 7, qi = tk & 7;
            const int gwin = gb * 8 + win;
            const int w15  = gwin & 32767;
            const int pz = w15 >> 10, py = (w15 >> 5) & 31, px = w15 & 31;

            uint4 qb = *(const uint4*)(s_qkv + (win * 8 + qi) * ROWB + hh * 16);
            float2 q0 = upk(qb.x), q1 = upk(qb.y), q2 = upk(qb.z), q3 = upk(qb.w);

            const int xm = ((pz == 31) ? 4 : 0) | ((py == 31) ? 2 : 0) | ((px == 31) ? 1 : 0);

            const int cf0p = (hh >> 1) & 1, cf1p = hh >> 2, cf2p = hh & 1;
            const int cf0q = (qi >> 1) & 1, cf1q = qi >> 2, cf2q = qi & 1;
            const int ridx = 3 * (cf0p - cf0q + 1) + (cf1p - cf1q + 1) + (cf2p - cf2q + 1);

            float rbv[8];
            {
                float4 r0 = __ldg((const float4*)(rpb + ridx * 8));
                float4 r1 = __ldg((const float4*)(rpb + ridx * 8 + 4));
                rbv[0] = r0.x; rbv[1] = r0.y; rbv[2] = r0.z; rbv[3] = r0.w;
                rbv[4] = r1.x; rbv[5] = r1.y; rbv[6] = r1.z; rbv[7] = r1.w;
            }

            float sc[8];
            float den = 0.f;
#pragma unroll
            for (int j = 0; j < 8; ++j) {
                uint4 kb = *(const uint4*)(s_qkv + (win * 8 + j) * ROWB + 128 + hh * 16);
                float2 k0 = upk(kb.x), k1 = upk(kb.y), k2 = upk(kb.z), k3 = upk(kb.w);
                float a;
                a = q0.x * k0.x;
                a = fmaf(q0.y, k0.y, a);
                a = fmaf(q1.x, k1.x, a);
                a = fmaf(q1.y, k1.y, a);
                a = fmaf(q2.x, k2.x, a);
                a = fmaf(q2.y, k2.y, a);
                a = fmaf(q3.x, k3.x, a);
                a = fmaf(q3.y, k3.y, a);
                a += rbv[j];
                if ((j ^ qi) & xm) a -= 100.f;
                sc[j] = __expf(a);
                den += sc[j];
            }
            float inv = 1.f / den;
#pragma unroll
            for (int j = 0; j < 8; ++j) sc[j] *= inv;

            float4 o0 = {0.f, 0.f, 0.f, 0.f}, o1 = {0.f, 0.f, 0.f, 0.f};
#pragma unroll
            for (int j = 0; j < 8; ++j) {
                uint4 vb = *(const uint4*)(s_qkv + (win * 8 + j) * ROWB + 256 + hh * 16);
                float2 v0 = upk(vb.x), v1 = upk(vb.y), v2 = upk(vb.z), v3 = upk(vb.w);
                o0.x = fmaf(sc[j], v0.x, o0.x);
                o0.y = fmaf(sc[j], v0.y, o0.y);
                o0.z = fmaf(sc[j], v1.x, o0.z);
                o0.w = fmaf(sc[j], v1.y, o0.w);
                o1.x = fmaf(sc[j], v2.x, o1.x);
                o1.y = fmaf(sc[j], v2.y, o1.y);
                o1.z = fmaf(sc[j], v3.x, o1.z);
                o1.w = fmaf(sc[j], v3.y, o1.w);
            }
            const int m = win * 8 + qi;
            uint4 ob;
            ob.x = pk(o0.x, o0.y);
            ob.y = pk(o0.z, o0.w);
            ob.z = pk(o1.x, o1.y);
            ob.w = pk(o1.z, o1.w);
            *(uint4*)(s_a + m * 128 + ((hh ^ (m & 7)) << 4)) = ob;
        }
        __syncthreads();   // [3]

        // ---- Phase 4: proj GEMM + window-reverse scatter + residual ----
        {
            float c2[4][4];
#pragma unroll
            for (int j = 0; j < 4; ++j)
#pragma unroll
                for (int r = 0; r < 4; ++r) c2[j][r] = 0.f;

#pragma unroll
            for (int k0 = 0; k0 < 4; ++k0) {
                uint32_t A[4], Bf[2][4];
                int colA = (((k0 << 1) + hi) ^ sw) << 4;
                ldsm_x4(A, ua + rowAoff + colA);
                uint32_t rb = uw + (uint32_t)(24576 + k0 * 2048 + l15 * 128);
                ldsm_x4t(Bf[0], rb + colB0);
                ldsm_x4t(Bf[1], rb + colB1);
#pragma unroll
                for (int j = 0; j < 4; ++j)
                    mma16(c2[j], A, &Bf[j >> 1][(j & 1) * 2]);
            }

            int offr[2];
#pragma unroll
            for (int i = 0; i < 2; ++i) {
                int m = R + g + i * 8;
                int gwin = gb * 8 + (m >> 3);
                int bb   = gwin >> 15;
                int w15  = gwin & 32767;
                int pz = w15 >> 10, py = (w15 >> 5) & 31, px = w15 & 31;
                int s = m & 7;
                int px1 = ((px & 15) << 1) | (s >> 2);
                int py1 = ((py & 15) << 1) | (px >> 4);
                int a2  = (py >> 4) & 1;
                int b2  = (s >> 1) & 1;
                int cc2 = s & 1;
                int gg = (pz << 5) + py1;
                gg = (gg << 1) + b2;
                gg = (gg << 1) + a2;
                gg = (gg << 5) + px1;
                gg = (gg << 1) + cc2;
                int dd  = ((gg >> 12) + 1) & 63;
                int hh2 = ((gg >> 6) + 1) & 63;
                int ww2 = (gg + 1) & 63;
                offr[i] = (bb << 24) + ((((dd << 12) | (hh2 << 6) | ww2)) << 6);
            }
#pragma unroll
            for (int j = 0; j < 4; ++j) {
                int col = Cb + j * 8 + tg * 2;
                float b0 = __ldg(projb + col);
                float b1 = __ldg(projb + col + 1);
#pragma unroll
                for (int i = 0; i < 2; ++i) {
                    float2 rx = *(const float2*)(x + offr[i] + col);
                    float2 o;
                    o.x = c2[j][2 * i]     + b0 + rx.x;
                    o.y = c2[j][2 * i + 1] + b1 + rx.y;
                    *(float2*)(x1 + offr[i] + col) = o;
                }
            }
        }
    }
}

// ---------------------------------------------------------------------------
// MLP kernel (persistent, R13-proven): weights staged once, register-chained
// GEMM1->GELU->GEMM2. 256 threads, 128 tokens/iter, 80KB smem, 2 blocks/SM.
// ---------------------------------------------------------------------------
__global__ void __launch_bounds__(256, 2) swin_mlp_bf16_kernel(
    float* __restrict__ io,
    const float* __restrict__ n2g, const float* __restrict__ n2b,
    const float* __restrict__ b1, const float* __restrict__ b2)
{
    extern __shared__ __align__(16) uint8_t smem[];
    uint8_t* s_a  = smem;                   // 16384
    uint8_t* s_w1 = smem + 16384;           // 32768
    uint8_t* s_w2 = smem + 49152;           // 32768

    const int tid  = threadIdx.x;
    const int lane = tid & 31;
    const int wrp  = tid >> 5;
    const int g    = lane >> 2, tg = lane & 3;
    const int l15  = lane & 15;
    const int hi   = lane >> 4;
    const int sw   = lane & 7;

    const uint32_t uaa = s2u(s_a);
    const uint32_t uw1 = s2u(s_w1);
    const uint32_t uw2 = s2u(s_w2);

    // ---- stage ALL weights once (identity uint4 copies) ----
    {
        uint4* d1 = (uint4*)s_w1;
        uint4* d2 = (uint4*)s_w2;
        const uint4* g1 = (const uint4*)gW1b;
        const uint4* g2 = (const uint4*)gW2b;
#pragma unroll
        for (int it = 0; it < 8; ++it) {
            d1[it * 256 + tid] = g1[it * 256 + tid];
            d2[it * 256 + tid] = g2[it * 256 + tid];
        }
    }

    const uint32_t rowA = (uint32_t)(wrp * 16 + l15) * 128;

    for (int tb = blockIdx.x; tb < 4096; tb += gridDim.x) {
        const int base = tb * 8192;
        __syncthreads();   // protect s_a across iterations (and weights on iter 0)

        // ---- LayerNorm2 -> s_a (bf16 swizzled) ----
        {
            const int mb = tid >> 2;
            const int cq = (tid & 3) << 4;
            const int c0 = (tid & 3) << 1;
            float4 g0 = *(const float4*)(n2g + cq);
            float4 g1 = *(const float4*)(n2g + cq + 4);
            float4 g2 = *(const float4*)(n2g + cq + 8);
            float4 g3 = *(const float4*)(n2g + cq + 12);
            float4 e0 = *(const float4*)(n2b + cq);
            float4 e1 = *(const float4*)(n2b + cq + 4);
            float4 e2 = *(const float4*)(n2b + cq + 8);
            float4 e3 = *(const float4*)(n2b + cq + 12);
#pragma unroll
            for (int p = 0; p < 2; ++p) {
                int m = p * 64 + mb;
                const float* src = io + base + m * 64 + cq;
                float4 v[4];
                float sm = 0.f, sq = 0.f;
#pragma unroll
                for (int f = 0; f < 4; ++f) {
                    v[f] = *(const float4*)(src + f * 4);
                    sm += v[f].x + v[f].y + v[f].z + v[f].w;
                    sq += v[f].x * v[f].x + v[f].y * v[f].y + v[f].z * v[f].z + v[f].w * v[f].w;
                }
                sm += __shfl_xor_sync(0xffffffffu, sm, 1);
                sq += __shfl_xor_sync(0xffffffffu, sq, 1);
                sm += __shfl_xor_sync(0xffffffffu, sm, 2);
                sq += __shfl_xor_sync(0xffffffffu, sq, 2);
                float mu = sm * 0.015625f;
                float rs = rsqrtf(fmaxf(sq * 0.015625f - mu * mu, 0.f) + 1e-5f);
                uint4 o;
                o.x = pk((v[0].x - mu) * rs * g0.x + e0.x, (v[0].y - mu) * rs * g0.y + e0.y);
                o.y = pk((v[0].z - mu) * rs * g0.z + e0.z, (v[0].w - mu) * rs * g0.w + e0.w);
                o.z = pk((v[1].x - mu) * rs * g1.x + e1.x, (v[1].y - mu) * rs * g1.y + e1.y);
                o.w = pk((v[1].z - mu) * rs * g1.z + e1.z, (v[1].w - mu) * rs * g1.w + e1.w);
                *(uint4*)(s_a + m * 128 + ((c0 ^ (m & 7)) << 4)) = o;
                o.x = pk((v[2].x - mu) * rs * g2.x + e2.x, (v[2].y - mu) * rs * g2.y + e2.y);
                o.y = pk((v[2].z - mu) * rs * g2.z + e2.z, (v[2].w - mu) * rs * g2.w + e2.w);
                o.z = pk((v[3].x - mu) * rs * g3.x + e3.x, (v[3].y - mu) * rs * g3.y + e3.y);
                o.w = pk((v[3].z - mu) * rs * g3.z + e3.z, (v[3].w - mu) * rs * g3.w + e3.w);
                *(uint4*)(s_a + m * 128 + (((c0 + 1) ^ (m & 7)) << 4)) = o;
            }
        }
        __syncthreads();

        uint32_t Afr[4][4];
#pragma unroll
        for (int k0 = 0; k0 < 4; ++k0)
            ldsm_x4(Afr[k0], uaa + rowA + ((((k0 << 1) + hi) ^ sw) << 4));

        float c2[8][4];
#pragma unroll
        for (int j = 0; j < 8; ++j)
#pragma unroll
            for (int r = 0; r < 4; ++r) c2[j][r] = 0.f;

#pragma unroll
        for (int nc = 0; nc < 4; ++nc) {
            float f1[8][4];
#pragma unroll
            for (int j = 0; j < 8; ++j)
#pragma unroll
                for (int r = 0; r < 4; ++r) f1[j][r] = 0.f;

#pragma unroll
            for (int k0 = 0; k0 < 4; ++k0) {
                uint32_t Bf[4][4];
                uint32_t rb = uw1 + (uint32_t)(nc * 8192 + k0 * 2048 + l15 * 128);
#pragma unroll
                for (int t = 0; t < 4; ++t)
                    ldsm_x4t(Bf[t], rb + ((((t << 1) + hi) ^ sw) << 4));
#pragma unroll
                for (int j = 0; j < 8; ++j)
                    mma16(f1[j], Afr[k0], &Bf[j >> 1][(j & 1) * 2]);
            }

            uint32_t Ha[4][4];
#pragma unroll
            for (int j = 0; j < 8; ++j) {
                int col0 = nc * 64 + j * 8 + tg * 2;
                float bb0 = __ldg(b1 + col0);
                float bb1 = __ldg(b1 + col0 + 1);
                float h0 = gelu_fast(f1[j][0] + bb0);
                float h1 = gelu_fast(f1[j][1] + bb1);
                float h2 = gelu_fast(f1[j][2] + bb0);
                float h3 = gelu_fast(f1[j][3] + bb1);
                Ha[j >> 1][(j & 1) * 2]     = pk(h0, h1);
                Ha[j >> 1][(j & 1) * 2 + 1] = pk(h2, h3);
            }

#pragma unroll
            for (int kb = 0; kb < 4; ++kb) {
                uint32_t Bf[4][4];
                uint32_t rb = uw2 + (uint32_t)(nc * 8192 + kb * 2048 + l15 * 128);
#pragma unroll
                for (int t = 0; t < 4; ++t)
                    ldsm_x4t(Bf[t], rb + ((((t << 1) + hi) ^ sw) << 4));
#pragma unroll
                for (int j = 0; j < 8; ++j)
                    mma16(c2[j], Ha[kb], &Bf[j >> 1][(j & 1) * 2]);
            }
        }

        {
            int m0 = wrp * 16 + g;
            int m1 = m0 + 8;
#pragma unroll
            for (int j = 0; j < 8; ++j) {
                int col = j * 8 + tg * 2;
                float bb0 = __ldg(b2 + col);
                float bb1 = __ldg(b2 + col + 1);
                float2 r0 = *(const float2*)(io + base + m0 * 64 + col);
                float2 r1 = *(const float2*)(io + base + m1 * 64 + col);
                float2 o0, o1;
                o0.x = c2[j][0] + bb0 + r0.x;
                o0.y = c2[j][1] + bb1 + r0.y;
                o1.x = c2[j][2] + bb0 + r1.x;
                o1.y = c2[j][3] + bb1 + r1.y;
                *(float2*)(io + base + m0 * 64 + col) = o0;
                *(float2*)(io + base + m1 * 64 + col) = o1;
            }
        }
    }
}

extern "C" void kernel_launch(void* const* d_in, const int* in_sizes, int n_in,
                              void* d_out, int out_size)
{
    const float* x     = (const float*)d_in[0];
    const float* n1g   = (const float*)d_in[1];
    const float* n1b   = (const float*)d_in[2];
    const float* qkvw  = (const float*)d_in[3];
    const float* qkvb  = (const float*)d_in[4];
    const float* rpb   = (const float*)d_in[5];
    const float* projw = (const float*)d_in[6];
    const float* projb = (const float*)d_in[7];
    const float* n2g   = (const float*)d_in[8];
    const float* n2b   = (const float*)d_in[9];
    const float* w1    = (const float*)d_in[10];
    const float* b1    = (const float*)d_in[11];
    const float* w2    = (const float*)d_in[12];
    const float* b2    = (const float*)d_in[13];
    float* out = (float*)d_out;

    const int attn_smem = 8192 + 32768 + 64 * ROWB;       // 66560 B
    const int mlp_smem  = 16384 + 32768 + 32768;          // 81920 B
    cudaFuncSetAttribute(swin_attn_bf16_kernel,
                         cudaFuncAttributeMaxDynamicSharedMemorySize, attn_smem);
    cudaFuncSetAttribute(swin_mlp_bf16_kernel,
                         cudaFuncAttributeMaxDynamicSharedMemorySize, mlp_smem);

    cvt_weights_kernel<<<96, 64>>>(qkvw, projw, w1, w2);
    // persistent grids: 152 SMs x 3 and x 2
    swin_attn_bf16_kernel<<<456, 256, attn_smem>>>(
        x, n1g, n1b, qkvb, rpb, projb, out);
    swin_mlp_bf16_kernel<<<304, 256, mlp_smem>>>(out, n2g, n2b, b1, b2);
}